// round 12
// baseline (speedup 1.0000x reference)
#include <cuda_runtime.h>

#define EPS 0.1f
#define BB 64
#define II 1024
#define HH 4096
#define OO 256

__device__ float        g_w1norm[HH];
__device__ unsigned int g_done[4];   // zero-init; per replay: 0 -> 128 -> reset
__device__ unsigned int g_acks[4];   // zero-init; per replay: 0 -> 256 -> reset

// ---------------------------------------------------------------------------
// K1: W1_norm — separate 512-block kernel so the dispatcher schedules it
//   FIRST (it fits entirely: 4096 of 9472 warp slots). Block b covers rows
//   [8b, 8b+8) — all inside chunk (b>>7). After publishing its 8 norms it
//   fences and bumps g_done[chunk]. PDL trigger fires at entry so k_main's
//   blocks start launching (and loading W2/y) immediately.
// ---------------------------------------------------------------------------
__global__ void k_w1norm(const float* __restrict__ W1) {
#if __CUDA_ARCH__ >= 900
    cudaTriggerProgrammaticLaunchCompletion();
#endif
    const int lid = threadIdx.x & 31;
    const int wid = threadIdx.x >> 5;
    const int row = blockIdx.x * 8 + wid;
    const float4* r = reinterpret_cast<const float4*>(W1 + (size_t)row * II);
    float4 v[8];
    #pragma unroll
    for (int k = 0; k < 8; k++) v[k] = r[lid + k * 32];
    float s = 0.f;
    #pragma unroll
    for (int k = 0; k < 8; k++)
        s += fabsf(v[k].x) + fabsf(v[k].y) + fabsf(v[k].z) + fabsf(v[k].w);
    #pragma unroll
    for (int o = 16; o; o >>= 1) s += __shfl_down_sync(0xffffffffu, s, o);
    if (lid == 0) g_w1norm[row] = s;
    __syncthreads();
    __threadfence();                              // publish norms before flag
    if (threadIdx.x == 0) atomicAdd(&g_done[blockIdx.x >> 7], 1u);
}

// ---------------------------------------------------------------------------
// K2: nn + pert (R3 block layout), launched via PDL (overlaps k_w1norm).
//   bid <  256 : nn_output row i = bid — no dependency, runs immediately.
//   bid >= 256 : pert unit p = bid-256 (i=p>>2, c=p&3): load W2/y first,
//                spin (yielding) on g_done[c]==128, then the measured-fast
//                R2/R3 store stream. 256th acker per chunk resets the flags.
// ---------------------------------------------------------------------------
__global__ void k_main(const int* __restrict__ y,
                       const float* __restrict__ W2,
                       const float* __restrict__ bias2,
                       float* __restrict__ out_nn,
                       float* __restrict__ pert) {
    const int bid = blockIdx.x;
    const int lid = threadIdx.x & 31;
    const int wid = threadIdx.x >> 5;

    if (bid < 256) {
        // ---- nn_output row i ----
        const int i = bid;
        const float4* r = reinterpret_cast<const float4*>(W2 + (size_t)i * HH);
        float4 v[4];
        #pragma unroll
        for (int k = 0; k < 4; k++) v[k] = r[threadIdx.x + k * 256];
        float s = 0.f;
        #pragma unroll
        for (int k = 0; k < 4; k++) s += v[k].x + v[k].y + v[k].z + v[k].w;

        __shared__ float sm[8];
        #pragma unroll
        for (int o = 16; o; o >>= 1) s += __shfl_down_sync(0xffffffffu, s, o);
        if (lid == 0) sm[wid] = s;
        __syncthreads();
        __shared__ float total;
        if (threadIdx.x < 8) {
            float t = sm[threadIdx.x];
            #pragma unroll
            for (int o = 4; o; o >>= 1) t += __shfl_down_sync(0xffu, t, o);
            if (threadIdx.x == 0) total = t * (float)HH + bias2[i];
        }
        __syncthreads();
        if (threadIdx.x < BB)
            out_nn[(size_t)threadIdx.x * OO + i] = total;
        return;
    }

    // ---- pert ----
    const int p  = bid - 256;
    const int i  = p >> 2;
    const int c  = p & 3;
    const int j4 = c * 256 + threadIdx.x;

    __shared__ float yf[BB];
    if (threadIdx.x < BB) yf[threadIdx.x] = (float)y[(size_t)threadIdx.x * OO + i];

    // independent load first — overlaps the wait
    float4 w = reinterpret_cast<const float4*>(W2 + (size_t)i * HH)[j4];

    if (threadIdx.x == 0) {
        while (*(volatile unsigned int*)&g_done[c] < 128u)
            __nanosleep(128);
        __threadfence();                           // acquire norms
        if (atomicAdd(&g_acks[c], 1u) == 255u) {   // last waiter resets for replay
            *(volatile unsigned int*)&g_done[c] = 0u;
            *(volatile unsigned int*)&g_acks[c] = 0u;
        }
    }
    __syncthreads();                               // releases wait + covers yf

    float4 n = reinterpret_cast<const float4*>(g_w1norm)[j4];
    float4 s;
    s.x = -EPS * ((w.x > 0.f) ? 1.f : (w.x < 0.f) ? -1.f : 0.f) * n.x;
    s.y = -EPS * ((w.y > 0.f) ? 1.f : (w.y < 0.f) ? -1.f : 0.f) * n.y;
    s.z = -EPS * ((w.z > 0.f) ? 1.f : (w.z < 0.f) ? -1.f : 0.f) * n.z;
    s.w = -EPS * ((w.w > 0.f) ? 1.f : (w.w < 0.f) ? -1.f : 0.f) * n.w;

    float* base = pert + (size_t)i * HH + (size_t)j4 * 4;
    #pragma unroll 8
    for (int b = 0; b < BB; b++) {
        float yb = yf[b];
        float4 o;
        o.x = yb * s.x; o.y = yb * s.y; o.z = yb * s.z; o.w = yb * s.w;
        __stcs(reinterpret_cast<float4*>(base + (size_t)b * OO * HH), o);
    }
}

// ---------------------------------------------------------------------------
// launch — k_w1norm, then k_main overlapped via PDL (same stream)
// inputs: x[0] (unused), y[1], W1[2], W2[3], bias1[4] (unused), bias2[5]
// out layout: nn_output [B*O] then pert [B*O*H]
// ---------------------------------------------------------------------------
extern "C" void kernel_launch(void* const* d_in, const int* in_sizes, int n_in,
                              void* d_out, int out_size) {
    const int*   y     = (const int*)d_in[1];
    const float* W1    = (const float*)d_in[2];
    const float* W2    = (const float*)d_in[3];
    const float* bias2 = (const float*)d_in[5];

    float* out_nn = (float*)d_out;
    float* pert   = out_nn + (size_t)BB * OO;

    k_w1norm<<<512, 256>>>(W1);

    cudaLaunchAttribute attrs[1];
    attrs[0].id = cudaLaunchAttributeProgrammaticStreamSerialization;
    attrs[0].val.programmaticStreamSerializationAllowed = 1;

    cudaLaunchConfig_t cfg = {};
    cfg.gridDim  = dim3(256 + 1024);
    cfg.blockDim = dim3(256);
    cfg.dynamicSmemBytes = 0;
    cfg.stream   = 0;
    cfg.attrs    = attrs;
    cfg.numAttrs = 1;
    cudaLaunchKernelEx(&cfg, k_main, y, W2, bias2, out_nn, pert);
}